// round 9
// baseline (speedup 1.0000x reference)
#include <cuda_runtime.h>
#include <cuda_fp16.h>
#include <cstdint>

#define B_SZ  16
#define N_IN  6250
#define N_OUT 25000
#define CCH   64
#define SNB   9
#define NNZ   75000

// fp16 pooled [B][N_OUT][64] = 51.2 MB
__device__ unsigned short g_pooled_h[(size_t)B_SZ * N_OUT * CCH];
// W in mma-fragment order: [s][kk][nb][lane] -> (b0,b1), 72 KB
__device__ uint2 g_wfrag[SNB * 4 * 8 * 32];
// CSR scratch
__device__ int   g_cnt[N_OUT];
__device__ int   g_off[N_OUT + 1];
__device__ int   g_cur[N_OUT];
__device__ int   g_ecol[NNZ];
__device__ float g_eval[NNZ];

// ---------------------------------------------------------------------------
// helpers
// ---------------------------------------------------------------------------
__device__ __forceinline__ uint32_t smem_u32(const void* p) {
    uint32_t a;
    asm("{ .reg .u64 t; cvta.to.shared.u64 t, %1; cvt.u32.u64 %0, t; }"
        : "=r"(a) : "l"(p));
    return a;
}
__device__ __forceinline__ void cp16(uint32_t dst, const void* src) {
    asm volatile("cp.async.cg.shared.global [%0], [%1], 16;"
                 :: "r"(dst), "l"(src) : "memory");
}
__device__ __forceinline__ void cp_commit() {
    asm volatile("cp.async.commit_group;" ::: "memory");
}
template <int N>
__device__ __forceinline__ void cp_wait() {
    asm volatile("cp.async.wait_group %0;" :: "n"(N) : "memory");
}
__device__ __forceinline__ void ldm4(uint32_t* r, uint32_t addr) {
    asm volatile("ldmatrix.sync.aligned.m8n8.x4.shared.b16 {%0,%1,%2,%3}, [%4];"
                 : "=r"(r[0]), "=r"(r[1]), "=r"(r[2]), "=r"(r[3])
                 : "r"(addr));
}
__device__ __forceinline__ void mma16816(float* d, const uint32_t* a,
                                         const uint32_t* b) {
    asm volatile(
        "mma.sync.aligned.m16n8k16.row.col.f32.f16.f16.f32 "
        "{%0,%1,%2,%3},{%4,%5,%6,%7},{%8,%9},{%0,%1,%2,%3};"
        : "+f"(d[0]), "+f"(d[1]), "+f"(d[2]), "+f"(d[3])
        : "r"(a[0]), "r"(a[1]), "r"(a[2]), "r"(a[3]), "r"(b[0]), "r"(b[1]));
}

// ---------------------------------------------------------------------------
// prep: csr_zero (blocks 0..97) + W fragment build (blocks 98..133)
// ---------------------------------------------------------------------------
#define ZERO_BLOCKS 98
#define WFRAG_BLOCKS 36
__global__ void prep_kernel(const float* __restrict__ W) {
    if (blockIdx.x < ZERO_BLOCKS) {
        int t = blockIdx.x * 256 + threadIdx.x;
        if (t < N_OUT) g_cnt[t] = 0;
        return;
    }
    int i = (blockIdx.x - ZERO_BLOCKS) * 256 + threadIdx.x;
    if (i >= SNB * 4 * 8 * 32) return;
    int l  = i & 31;
    int nb = (i >> 5) & 7;
    int kk = (i >> 8) & 3;
    int s  = i >> 10;
    int n  = nb * 8 + (l >> 2);
    int k0 = s * 64 + kk * 16 + (l & 3) * 2;
    __half2 b0 = __halves2half2(__float2half_rn(__ldg(W + (size_t)k0 * 64 + n)),
                                __float2half_rn(__ldg(W + (size_t)(k0 + 1) * 64 + n)));
    __half2 b1 = __halves2half2(__float2half_rn(__ldg(W + (size_t)(k0 + 8) * 64 + n)),
                                __float2half_rn(__ldg(W + (size_t)(k0 + 9) * 64 + n)));
    uint2 v;
    v.x = *reinterpret_cast<uint32_t*>(&b0);
    v.y = *reinterpret_cast<uint32_t*>(&b1);
    g_wfrag[i] = v;
}

// ---------------------------------------------------------------------------
// CSR build: hist -> scan -> scatter
// ---------------------------------------------------------------------------
__global__ void csr_hist(const int* __restrict__ tr) {
    int t = blockIdx.x * blockDim.x + threadIdx.x;
    if (t < NNZ) atomicAdd(&g_cnt[__ldg(tr + t)], 1);
}

#define SCAN_T 1024
#define ROWS_PER_T 25
__global__ void __launch_bounds__(SCAN_T) csr_scan() {
    __shared__ int s[SCAN_T];
    const int t = threadIdx.x;
    const int base = t * ROWS_PER_T;
    int local[ROWS_PER_T];
    int sum = 0;
#pragma unroll
    for (int i = 0; i < ROWS_PER_T; i++) {
        int r = base + i;
        local[i] = (r < N_OUT) ? g_cnt[r] : 0;
        sum += local[i];
    }
    s[t] = sum;
    __syncthreads();
    for (int ofs = 1; ofs < SCAN_T; ofs <<= 1) {
        int v = (t >= ofs) ? s[t - ofs] : 0;
        __syncthreads();
        s[t] += v;
        __syncthreads();
    }
    int run = s[t] - sum;
#pragma unroll
    for (int i = 0; i < ROWS_PER_T; i++) {
        int r = base + i;
        if (r < N_OUT) {
            g_off[r] = run;
            g_cur[r] = run;
            run += local[i];
        }
    }
    if (t == SCAN_T - 1) g_off[N_OUT] = NNZ;
}

__global__ void csr_scatter(const float* __restrict__ tv,
                            const int* __restrict__ tr,
                            const int* __restrict__ tc) {
    int t = blockIdx.x * blockDim.x + threadIdx.x;
    if (t >= NNZ) return;
    int row = __ldg(tr + t);
    int pos = atomicAdd(&g_cur[row], 1);
    g_ecol[pos] = __ldg(tc + t);
    g_eval[pos] = __ldg(tv + t);
}

// ---------------------------------------------------------------------------
// pool_gather: one warp per output row, fp32 reg accumulation -> fp16 store
// ---------------------------------------------------------------------------
__global__ void __launch_bounds__(256) pool_gather(const float* __restrict__ x) {
    int t = blockIdx.x * blockDim.x + threadIdx.x;
    if (t >= N_OUT * 32) return;
    const int row = t >> 5;
    const int r   = t & 31;
    const int cg  = r & 15;
    const int b0  = (r >> 4) * 8;

    const int start = g_off[row];
    const int end   = g_off[row + 1];

    float4 acc[8];
#pragma unroll
    for (int b = 0; b < 8; b++) acc[b] = make_float4(0.f, 0.f, 0.f, 0.f);

    const float4* xp = reinterpret_cast<const float4*>(x);
    for (int i = start; i < end; i++) {
        int col = __ldg(g_ecol + i);
        float v = __ldg(g_eval + i);
        const float4* src = xp + ((size_t)b0 * N_IN + col) * 16 + cg;
#pragma unroll
        for (int b = 0; b < 8; b++) {
            float4 xv = src[(size_t)b * N_IN * 16];
            acc[b].x += v * xv.x;
            acc[b].y += v * xv.y;
            acc[b].z += v * xv.z;
            acc[b].w += v * xv.w;
        }
    }
#pragma unroll
    for (int b = 0; b < 8; b++) {
        ushort4 h;
        h.x = __half_as_ushort(__float2half_rn(acc[b].x));
        h.y = __half_as_ushort(__float2half_rn(acc[b].y));
        h.z = __half_as_ushort(__float2half_rn(acc[b].z));
        h.w = __half_as_ushort(__float2half_rn(acc[b].w));
        *reinterpret_cast<ushort4*>(
            g_pooled_h + ((size_t)(b0 + b) * N_OUT + row) * CCH + cg * 4) = h;
    }
}

// ---------------------------------------------------------------------------
// persistent fused spiral gather + fp16 GEMM, continuous cross-item pipeline
// CTA: 128 rows x 64 cols, 256 threads, 8 warps (4x2), warp tile 32x32.
// Static item stride = grid (444 = 148 x 3). A-ring 3 x 16 KB spans items.
// ---------------------------------------------------------------------------
#define N_TILES   ((N_OUT + 127) / 128)     // 196
#define N_ITEMS   (N_TILES * B_SZ)          // 3136
#define GRID_P    444
#define STAGE_SZ  16384
#define NSTAGE    3
#define GEMM_SMEM (NSTAGE * STAGE_SZ)

__global__ void __launch_bounds__(256, 3) spiral_gemm_mma(
    const int*   __restrict__ sp,
    const float* __restrict__ bias,
    float*       __restrict__ out) {
    extern __shared__ char smem[];
    const uint32_t sbase = smem_u32(smem);

    const int tid = threadIdx.x;
    const int l   = tid & 31;
    const int wid = tid >> 5;
    const int wm  = wid >> 1;
    const int wn  = wid & 1;

    const int arow  = tid >> 1;
    const int ahalf = tid & 1;
    const int rx    = arow & 7;

    const uint2* wfW = g_wfrag + (wn * 4) * 32 + l;

    float bias8[4][2];
#pragma unroll
    for (int nj = 0; nj < 4; nj++) {
        int col = wn * 32 + nj * 8 + (l & 3) * 2;
        bias8[nj][0] = __ldg(bias + col);
        bias8[nj][1] = __ldg(bias + col + 1);
    }

    // staging cursor: leads compute by 2 slices, continuous across items
    int st_item = blockIdx.x;
    int st_s    = 0;
    int st_buf  = 0;

    auto stage_next = [&]() {
        if (st_item >= N_ITEMS) { cp_commit(); return; }
        const int bb = st_item & 15;
        const int n0 = (st_item >> 4) * 128;
        int nn = n0 + arow;
        if (nn >= N_OUT) nn = N_OUT - 1;
        const int idx = __ldg(sp + (size_t)nn * SNB + st_s);
        const char* srcA =
            (const char*)(g_pooled_h + ((size_t)bb * N_OUT + idx) * CCH) +
            ahalf * 64;
        uint32_t dstA = sbase + st_buf * STAGE_SZ + arow * 128;
#pragma unroll
        for (int j = 0; j < 4; j++) {
            int c = ahalf * 4 + j;
            cp16(dstA + ((c ^ rx) << 4), srcA + j * 16);
        }
        cp_commit();
        if (++st_buf == NSTAGE) st_buf = 0;
        if (++st_s == SNB) { st_s = 0; st_item += GRID_P; }
    };

    stage_next();
    stage_next();

    int cbuf = 0;
    for (int item = blockIdx.x; item < N_ITEMS; item += GRID_P) {
        const int bb = item & 15;
        const int n0 = (item >> 4) * 128;

        float acc[2][4][4];
#pragma unroll
        for (int mi = 0; mi < 2; mi++)
#pragma unroll
            for (int nj = 0; nj < 4; nj++)
#pragma unroll
                for (int j = 0; j < 4; j++) acc[mi][nj][j] = 0.f;

#pragma unroll
        for (int s = 0; s < SNB; s++) {
            cp_wait<1>();
            __syncthreads();      // all warps done with buffer (cbuf-1):
                                  // safe for stage_next to write (cbuf+2)%3
            stage_next();
            const uint32_t stg = sbase + cbuf * STAGE_SZ;
#pragma unroll
            for (int kk = 0; kk < 4; kk++) {
                uint32_t ah[2][4];
#pragma unroll
                for (int mi = 0; mi < 2; mi++) {
                    int row = wm * 32 + mi * 16 + (l & 15);
                    int c = kk * 2 + (l >> 4);
                    ldm4(ah[mi], stg + row * 128 + ((c ^ (row & 7)) << 4));
                }
                const uint2* wf = wfW + (size_t)(s * 4 + kk) * 8 * 32;
                uint2 bv[4];
#pragma unroll
                for (int nj = 0; nj < 4; nj++) bv[nj] = __ldg(wf + nj * 32);
#pragma unroll
                for (int mi = 0; mi < 2; mi++)
#pragma unroll
                    for (int nj = 0; nj < 4; nj++)
                        mma16816(acc[mi][nj], ah[mi], &bv[nj].x);
            }
            if (++cbuf == NSTAGE) cbuf = 0;
        }

        // ---- epilogue: bias + ELU + store (overlaps next item's staging) ----
#pragma unroll
        for (int mi = 0; mi < 2; mi++) {
#pragma unroll
            for (int half = 0; half < 2; half++) {
                int m = wm * 32 + mi * 16 + (l >> 2) + half * 8;
                int n = n0 + m;
                if (n >= N_OUT) continue;
                float* dst = out + ((size_t)bb * N_OUT + n) * CCH;
#pragma unroll
                for (int nj = 0; nj < 4; nj++) {
                    int col = wn * 32 + nj * 8 + (l & 3) * 2;
                    float t0 = acc[mi][nj][half * 2 + 0] + bias8[nj][0];
                    float t1 = acc[mi][nj][half * 2 + 1] + bias8[nj][1];
                    float2 o;
                    o.x = (t0 > 0.f) ? t0 : (__expf(t0) - 1.f);
                    o.y = (t1 > 0.f) ? t1 : (__expf(t1) - 1.f);
                    *reinterpret_cast<float2*>(dst + col) = o;
                }
            }
        }
    }
}

// ---------------------------------------------------------------------------
extern "C" void kernel_launch(void* const* d_in, const int* in_sizes, int n_in,
                              void* d_out, int out_size) {
    const float* x    = (const float*)d_in[0];
    const float* tv   = (const float*)d_in[1];
    const int*   tr   = (const int*)d_in[2];
    const int*   tc   = (const int*)d_in[3];
    const int*   sp   = (const int*)d_in[4];
    const float* W    = (const float*)d_in[5];
    const float* bias = (const float*)d_in[6];
    float* out = (float*)d_out;

    static bool attr_set = false;
    if (!attr_set) {
        cudaFuncSetAttribute(spiral_gemm_mma,
                             cudaFuncAttributeMaxDynamicSharedMemorySize,
                             GEMM_SMEM);
        attr_set = true;
    }

    prep_kernel<<<ZERO_BLOCKS + WFRAG_BLOCKS, 256>>>(W);
    csr_hist<<<(NNZ + 255) / 256, 256>>>(tr);
    csr_scan<<<1, SCAN_T>>>();
    csr_scatter<<<(NNZ + 255) / 256, 256>>>(tv, tr, tc);
    pool_gather<<<(N_OUT * 32 + 255) / 256, 256>>>(x);

    spiral_gemm_mma<<<GRID_P, 256, GEMM_SMEM>>>(sp, bias, out);
}

// round 10
// speedup vs baseline: 1.0894x; 1.0894x over previous
#include <cuda_runtime.h>
#include <cuda_fp16.h>
#include <cstdint>

#define B_SZ  16
#define N_IN  6250
#define N_OUT 25000
#define CCH   64
#define SNB   9
#define NNZ   75000

// fp16 pooled [B][N_OUT][64] = 51.2 MB
__device__ unsigned short g_pooled_h[(size_t)B_SZ * N_OUT * CCH];
// fp16 x [B][N_IN][64] = 12.8 MB
__device__ unsigned short g_x_h[(size_t)B_SZ * N_IN * CCH];
// W in mma-fragment order: [s][kk][nb][lane] -> (b0,b1), 72 KB
__device__ uint2 g_wfrag[SNB * 4 * 8 * 32];
// CSR scratch
__device__ int   g_cnt[N_OUT];
__device__ int   g_off[N_OUT + 1];
__device__ int   g_cur[N_OUT];
__device__ int   g_ecol[NNZ];
__device__ float g_eval[NNZ];

// ---------------------------------------------------------------------------
// helpers
// ---------------------------------------------------------------------------
__device__ __forceinline__ uint32_t smem_u32(const void* p) {
    uint32_t a;
    asm("{ .reg .u64 t; cvta.to.shared.u64 t, %1; cvt.u32.u64 %0, t; }"
        : "=r"(a) : "l"(p));
    return a;
}
__device__ __forceinline__ void cp16(uint32_t dst, const void* src) {
    asm volatile("cp.async.cg.shared.global [%0], [%1], 16;"
                 :: "r"(dst), "l"(src) : "memory");
}
__device__ __forceinline__ void cp_commit() {
    asm volatile("cp.async.commit_group;" ::: "memory");
}
template <int N>
__device__ __forceinline__ void cp_wait() {
    asm volatile("cp.async.wait_group %0;" :: "n"(N) : "memory");
}
__device__ __forceinline__ void ldm4(uint32_t* r, uint32_t addr) {
    asm volatile("ldmatrix.sync.aligned.m8n8.x4.shared.b16 {%0,%1,%2,%3}, [%4];"
                 : "=r"(r[0]), "=r"(r[1]), "=r"(r[2]), "=r"(r[3])
                 : "r"(addr));
}
__device__ __forceinline__ void mma16816(float* d, const uint32_t* a,
                                         const uint32_t* b) {
    asm volatile(
        "mma.sync.aligned.m16n8k16.row.col.f32.f16.f16.f32 "
        "{%0,%1,%2,%3},{%4,%5,%6,%7},{%8,%9},{%0,%1,%2,%3};"
        : "+f"(d[0]), "+f"(d[1]), "+f"(d[2]), "+f"(d[3])
        : "r"(a[0]), "r"(a[1]), "r"(a[2]), "r"(a[3]), "r"(b[0]), "r"(b[1]));
}

// ---------------------------------------------------------------------------
// prep: W fragment build (blocks 0..35) + x fp32->fp16 (blocks 36..6285)
// ---------------------------------------------------------------------------
#define WFRAG_BLOCKS 36
#define XCONV_BLOCKS ((B_SZ * N_IN * CCH / 4 + 255) / 256)   // 6250
__global__ void prep_kernel(const float* __restrict__ W,
                            const float* __restrict__ x) {
    if (blockIdx.x < WFRAG_BLOCKS) {
        int i = blockIdx.x * 256 + threadIdx.x;
        if (i >= SNB * 4 * 8 * 32) return;
        int l  = i & 31;
        int nb = (i >> 5) & 7;
        int kk = (i >> 8) & 3;
        int s  = i >> 10;
        int n  = nb * 8 + (l >> 2);
        int k0 = s * 64 + kk * 16 + (l & 3) * 2;
        __half2 b0 = __halves2half2(
            __float2half_rn(__ldg(W + (size_t)k0 * 64 + n)),
            __float2half_rn(__ldg(W + (size_t)(k0 + 1) * 64 + n)));
        __half2 b1 = __halves2half2(
            __float2half_rn(__ldg(W + (size_t)(k0 + 8) * 64 + n)),
            __float2half_rn(__ldg(W + (size_t)(k0 + 9) * 64 + n)));
        uint2 v;
        v.x = *reinterpret_cast<uint32_t*>(&b0);
        v.y = *reinterpret_cast<uint32_t*>(&b1);
        g_wfrag[i] = v;
        return;
    }
    size_t i = (size_t)(blockIdx.x - WFRAG_BLOCKS) * 256 + threadIdx.x;
    const size_t total = (size_t)B_SZ * N_IN * CCH / 4;
    if (i >= total) return;
    float4 v = reinterpret_cast<const float4*>(x)[i];
    ushort4 h;
    h.x = __half_as_ushort(__float2half_rn(v.x));
    h.y = __half_as_ushort(__float2half_rn(v.y));
    h.z = __half_as_ushort(__float2half_rn(v.z));
    h.w = __half_as_ushort(__float2half_rn(v.w));
    reinterpret_cast<ushort4*>(g_x_h)[i] = h;
}

// ---------------------------------------------------------------------------
// CSR build: hist -> scan -> scatter  (g_cnt zeroed via cudaMemsetAsync)
// ---------------------------------------------------------------------------
__global__ void csr_hist(const int* __restrict__ tr) {
    int t = blockIdx.x * blockDim.x + threadIdx.x;
    if (t < NNZ) atomicAdd(&g_cnt[__ldg(tr + t)], 1);
}

#define SCAN_T 1024
#define ROWS_PER_T 25
__global__ void __launch_bounds__(SCAN_T) csr_scan() {
    __shared__ int s[SCAN_T];
    const int t = threadIdx.x;
    const int base = t * ROWS_PER_T;
    int local[ROWS_PER_T];
    int sum = 0;
#pragma unroll
    for (int i = 0; i < ROWS_PER_T; i++) {
        int r = base + i;
        local[i] = (r < N_OUT) ? g_cnt[r] : 0;
        sum += local[i];
    }
    s[t] = sum;
    __syncthreads();
    for (int ofs = 1; ofs < SCAN_T; ofs <<= 1) {
        int v = (t >= ofs) ? s[t - ofs] : 0;
        __syncthreads();
        s[t] += v;
        __syncthreads();
    }
    int run = s[t] - sum;
#pragma unroll
    for (int i = 0; i < ROWS_PER_T; i++) {
        int r = base + i;
        if (r < N_OUT) {
            g_off[r] = run;
            g_cur[r] = run;
            run += local[i];
        }
    }
    if (t == SCAN_T - 1) g_off[N_OUT] = NNZ;
}

__global__ void csr_scatter(const float* __restrict__ tv,
                            const int* __restrict__ tr,
                            const int* __restrict__ tc) {
    int t = blockIdx.x * blockDim.x + threadIdx.x;
    if (t >= NNZ) return;
    int row = __ldg(tr + t);
    int pos = atomicAdd(&g_cur[row], 1);
    g_ecol[pos] = __ldg(tc + t);
    g_eval[pos] = __ldg(tv + t);
}

// ---------------------------------------------------------------------------
// pool_gather: one warp per output row; x read as fp16 (half the traffic),
// fp32 register accumulation, fp16 store.
// lane = cg (0..15, 4-channel group) x b-half (0..1, 8 batches each)
// ---------------------------------------------------------------------------
__global__ void __launch_bounds__(256) pool_gather() {
    int t = blockIdx.x * blockDim.x + threadIdx.x;
    if (t >= N_OUT * 32) return;
    const int row = t >> 5;
    const int r   = t & 31;
    const int cg  = r & 15;
    const int b0  = (r >> 4) * 8;

    const int start = g_off[row];
    const int end   = g_off[row + 1];

    float4 acc[8];
#pragma unroll
    for (int b = 0; b < 8; b++) acc[b] = make_float4(0.f, 0.f, 0.f, 0.f);

    for (int i = start; i < end; i++) {
        int col = __ldg(g_ecol + i);
        float v = __ldg(g_eval + i);
        const uint2* src = reinterpret_cast<const uint2*>(
            g_x_h + ((size_t)b0 * N_IN + col) * CCH + cg * 4);
#pragma unroll
        for (int b = 0; b < 8; b++) {
            uint2 raw = src[(size_t)b * N_IN * 16];
            __half2 p0 = *reinterpret_cast<__half2*>(&raw.x);
            __half2 p1 = *reinterpret_cast<__half2*>(&raw.y);
            float2 f0 = __half22float2(p0);
            float2 f1 = __half22float2(p1);
            acc[b].x += v * f0.x;
            acc[b].y += v * f0.y;
            acc[b].z += v * f1.x;
            acc[b].w += v * f1.y;
        }
    }
#pragma unroll
    for (int b = 0; b < 8; b++) {
        ushort4 h;
        h.x = __half_as_ushort(__float2half_rn(acc[b].x));
        h.y = __half_as_ushort(__float2half_rn(acc[b].y));
        h.z = __half_as_ushort(__float2half_rn(acc[b].z));
        h.w = __half_as_ushort(__float2half_rn(acc[b].w));
        *reinterpret_cast<ushort4*>(
            g_pooled_h + ((size_t)(b0 + b) * N_OUT + row) * CCH + cg * 4) = h;
    }
}

// ---------------------------------------------------------------------------
// fused spiral gather + fp16 GEMM (B from register fragments) + bias + ELU
// CTA: 128 rows x 64 cols; 256 threads = 8 warps (4x2), warp tile 32x32.
// SMEM: A-only ring, 3 x 16 KB = 48 KB -> 3 CTAs/SM.  (identical to R8)
// ---------------------------------------------------------------------------
#define STAGE_SZ  16384
#define NSTAGE    3
#define GEMM_SMEM (NSTAGE * STAGE_SZ)

__global__ void __launch_bounds__(256, 3) spiral_gemm_mma(
    const int*   __restrict__ sp,
    const float* __restrict__ bias,
    float*       __restrict__ out) {
    extern __shared__ char smem[];
    const uint32_t sbase = smem_u32(smem);

    const int tid = threadIdx.x;
    const int l   = tid & 31;
    const int wid = tid >> 5;
    const int wm  = wid >> 1;
    const int wn  = wid & 1;
    const int b   = blockIdx.y;
    const int n0  = blockIdx.x * 128;

    const int arow  = tid >> 1;
    const int ahalf = tid & 1;
    const int rx    = arow & 7;

    const unsigned short* basePH = g_pooled_h + (size_t)b * N_OUT * CCH;
    const uint2* wfW = g_wfrag + (wn * 4) * 32 + l;

    float acc[2][4][4];
#pragma unroll
    for (int mi = 0; mi < 2; mi++)
#pragma unroll
        for (int nj = 0; nj < 4; nj++)
#pragma unroll
            for (int j = 0; j < 4; j++) acc[mi][nj][j] = 0.f;

    int nn = n0 + arow;
    if (nn >= N_OUT) nn = N_OUT - 1;

    int sidx[SNB];
#pragma unroll
    for (int s = 0; s < SNB; s++) sidx[s] = __ldg(sp + (size_t)nn * SNB + s);

    auto stage = [&](int s) {
        const uint32_t stg = sbase + (s % NSTAGE) * STAGE_SZ;
        const char* srcA =
            (const char*)(basePH + (size_t)sidx[s] * CCH) + ahalf * 64;
        uint32_t dstA = stg + arow * 128;
#pragma unroll
        for (int j = 0; j < 4; j++) {
            int c = ahalf * 4 + j;
            cp16(dstA + ((c ^ rx) << 4), srcA + j * 16);
        }
        cp_commit();
    };

    auto compute = [&](int s) {
        const uint32_t stg = sbase + (s % NSTAGE) * STAGE_SZ;
#pragma unroll
        for (int kk = 0; kk < 4; kk++) {
            uint32_t ah[2][4];
#pragma unroll
            for (int mi = 0; mi < 2; mi++) {
                int row = wm * 32 + mi * 16 + (l & 15);
                int c = kk * 2 + (l >> 4);
                ldm4(ah[mi], stg + row * 128 + ((c ^ (row & 7)) << 4));
            }
            const uint2* wf = wfW + (size_t)(s * 4 + kk) * 8 * 32;
            uint2 bv[4];
#pragma unroll
            for (int nj = 0; nj < 4; nj++) bv[nj] = __ldg(wf + nj * 32);
#pragma unroll
            for (int mi = 0; mi < 2; mi++)
#pragma unroll
                for (int nj = 0; nj < 4; nj++)
                    mma16816(acc[mi][nj], ah[mi], &bv[nj].x);
        }
    };

    stage(0);
    stage(1);
#pragma unroll
    for (int s = 0; s < SNB; s++) {
        cp_wait<1>();
        __syncthreads();
        if (s + 2 < SNB) stage(s + 2);
        else cp_commit();
        compute(s);
    }

    float bias8[4][2];
#pragma unroll
    for (int nj = 0; nj < 4; nj++) {
        int col = wn * 32 + nj * 8 + (l & 3) * 2;
        bias8[nj][0] = __ldg(bias + col);
        bias8[nj][1] = __ldg(bias + col + 1);
    }
#pragma unroll
    for (int mi = 0; mi < 2; mi++) {
#pragma unroll
        for (int half = 0; half < 2; half++) {
            int m = wm * 32 + mi * 16 + (l >> 2) + half * 8;
            int n = n0 + m;
            if (n >= N_OUT) continue;
            float* dst = out + ((size_t)b * N_OUT + n) * CCH;
#pragma unroll
            for (int nj = 0; nj < 4; nj++) {
                int col = wn * 32 + nj * 8 + (l & 3) * 2;
                float t0 = acc[mi][nj][half * 2 + 0] + bias8[nj][0];
                float t1 = acc[mi][nj][half * 2 + 1] + bias8[nj][1];
                float2 o;
                o.x = (t0 > 0.f) ? t0 : (__expf(t0) - 1.f);
                o.y = (t1 > 0.f) ? t1 : (__expf(t1) - 1.f);
                *reinterpret_cast<float2*>(dst + col) = o;
            }
        }
    }
}

// ---------------------------------------------------------------------------
extern "C" void kernel_launch(void* const* d_in, const int* in_sizes, int n_in,
                              void* d_out, int out_size) {
    const float* x    = (const float*)d_in[0];
    const float* tv   = (const float*)d_in[1];
    const int*   tr   = (const int*)d_in[2];
    const int*   tc   = (const int*)d_in[3];
    const int*   sp   = (const int*)d_in[4];
    const float* W    = (const float*)d_in[5];
    const float* bias = (const float*)d_in[6];
    float* out = (float*)d_out;

    static void* cnt_ptr = nullptr;
    static bool attr_set = false;
    if (!attr_set) {
        cudaFuncSetAttribute(spiral_gemm_mma,
                             cudaFuncAttributeMaxDynamicSharedMemorySize,
                             GEMM_SMEM);
        cudaGetSymbolAddress(&cnt_ptr, g_cnt);
        attr_set = true;
    }

    cudaMemsetAsync(cnt_ptr, 0, N_OUT * sizeof(int), 0);
    prep_kernel<<<WFRAG_BLOCKS + XCONV_BLOCKS, 256>>>(W, x);
    csr_hist<<<(NNZ + 255) / 256, 256>>>(tr);
    csr_scan<<<1, SCAN_T>>>();
    csr_scatter<<<(NNZ + 255) / 256, 256>>>(tv, tr, tc);
    pool_gather<<<(N_OUT * 32 + 255) / 256, 256>>>();

    dim3 grid((N_OUT + 127) / 128, B_SZ);
    spiral_gemm_mma<<<grid, 256, GEMM_SMEM>>>(sp, bias, out);
}

// round 11
// speedup vs baseline: 1.1006x; 1.0103x over previous
#include <cuda_runtime.h>
#include <cuda_fp16.h>
#include <cstdint>

#define B_SZ  16
#define N_IN  6250
#define N_OUT 25000
#define CCH   64
#define SNB   9
#define NNZ   75000

// fp16 pooled [B][N_OUT][64] = 51.2 MB
__device__ unsigned short g_pooled_h[(size_t)B_SZ * N_OUT * CCH];
// W in mma-fragment order: [s][kk][nb][lane] -> (b0,b1), 72 KB
__device__ uint2 g_wfrag[SNB * 4 * 8 * 32];
// CSR scratch
__device__ int   g_cnt[N_OUT];
__device__ int   g_off[N_OUT + 1];
__device__ int   g_cur[N_OUT];
__device__ int   g_ecol[NNZ];
__device__ float g_eval[NNZ];

// ---------------------------------------------------------------------------
// helpers
// ---------------------------------------------------------------------------
__device__ __forceinline__ uint32_t smem_u32(const void* p) {
    uint32_t a;
    asm("{ .reg .u64 t; cvta.to.shared.u64 t, %1; cvt.u32.u64 %0, t; }"
        : "=r"(a) : "l"(p));
    return a;
}
__device__ __forceinline__ void cp16(uint32_t dst, const void* src) {
    asm volatile("cp.async.cg.shared.global [%0], [%1], 16;"
                 :: "r"(dst), "l"(src) : "memory");
}
__device__ __forceinline__ void cp_commit() {
    asm volatile("cp.async.commit_group;" ::: "memory");
}
template <int N>
__device__ __forceinline__ void cp_wait() {
    asm volatile("cp.async.wait_group %0;" :: "n"(N) : "memory");
}
__device__ __forceinline__ void ldm4(uint32_t* r, uint32_t addr) {
    asm volatile("ldmatrix.sync.aligned.m8n8.x4.shared.b16 {%0,%1,%2,%3}, [%4];"
                 : "=r"(r[0]), "=r"(r[1]), "=r"(r[2]), "=r"(r[3])
                 : "r"(addr));
}
__device__ __forceinline__ void mma16816(float* d, const uint32_t* a,
                                         const uint32_t* b) {
    asm volatile(
        "mma.sync.aligned.m16n8k16.row.col.f32.f16.f16.f32 "
        "{%0,%1,%2,%3},{%4,%5,%6,%7},{%8,%9},{%0,%1,%2,%3};"
        : "+f"(d[0]), "+f"(d[1]), "+f"(d[2]), "+f"(d[3])
        : "r"(a[0]), "r"(a[1]), "r"(a[2]), "r"(a[3]), "r"(b[0]), "r"(b[1]));
}

// ---------------------------------------------------------------------------
// prep: W fragment build (blocks 0..35) + csr_hist (blocks 36..328)
// g_cnt is zeroed by cudaMemsetAsync before this launch.
// ---------------------------------------------------------------------------
#define WFRAG_BLOCKS 36
#define HIST_BLOCKS  ((NNZ + 255) / 256)      // 293
__global__ void prep_kernel(const float* __restrict__ W,
                            const int* __restrict__ tr) {
    if (blockIdx.x < WFRAG_BLOCKS) {
        int i = blockIdx.x * 256 + threadIdx.x;
        if (i >= SNB * 4 * 8 * 32) return;
        int l  = i & 31;
        int nb = (i >> 5) & 7;
        int kk = (i >> 8) & 3;
        int s  = i >> 10;
        int n  = nb * 8 + (l >> 2);
        int k0 = s * 64 + kk * 16 + (l & 3) * 2;
        __half2 b0 = __halves2half2(
            __float2half_rn(__ldg(W + (size_t)k0 * 64 + n)),
            __float2half_rn(__ldg(W + (size_t)(k0 + 1) * 64 + n)));
        __half2 b1 = __halves2half2(
            __float2half_rn(__ldg(W + (size_t)(k0 + 8) * 64 + n)),
            __float2half_rn(__ldg(W + (size_t)(k0 + 9) * 64 + n)));
        uint2 v;
        v.x = *reinterpret_cast<uint32_t*>(&b0);
        v.y = *reinterpret_cast<uint32_t*>(&b1);
        g_wfrag[i] = v;
        return;
    }
    int t = (blockIdx.x - WFRAG_BLOCKS) * 256 + threadIdx.x;
    if (t < NNZ) atomicAdd(&g_cnt[__ldg(tr + t)], 1);
}

// ---------------------------------------------------------------------------
// CSR build: scan -> scatter
// ---------------------------------------------------------------------------
#define SCAN_T 1024
#define ROWS_PER_T 25
__global__ void __launch_bounds__(SCAN_T) csr_scan() {
    __shared__ int s[SCAN_T];
    const int t = threadIdx.x;
    const int base = t * ROWS_PER_T;
    int local[ROWS_PER_T];
    int sum = 0;
#pragma unroll
    for (int i = 0; i < ROWS_PER_T; i++) {
        int r = base + i;
        local[i] = (r < N_OUT) ? g_cnt[r] : 0;
        sum += local[i];
    }
    s[t] = sum;
    __syncthreads();
    for (int ofs = 1; ofs < SCAN_T; ofs <<= 1) {
        int v = (t >= ofs) ? s[t - ofs] : 0;
        __syncthreads();
        s[t] += v;
        __syncthreads();
    }
    int run = s[t] - sum;
#pragma unroll
    for (int i = 0; i < ROWS_PER_T; i++) {
        int r = base + i;
        if (r < N_OUT) {
            g_off[r] = run;
            g_cur[r] = run;
            run += local[i];
        }
    }
    if (t == SCAN_T - 1) g_off[N_OUT] = NNZ;
}

__global__ void csr_scatter(const float* __restrict__ tv,
                            const int* __restrict__ tr,
                            const int* __restrict__ tc) {
    int t = blockIdx.x * blockDim.x + threadIdx.x;
    if (t >= NNZ) return;
    int row = __ldg(tr + t);
    int pos = atomicAdd(&g_cur[row], 1);
    g_ecol[pos] = __ldg(tc + t);
    g_eval[pos] = __ldg(tv + t);
}

// ---------------------------------------------------------------------------
// pool_gather: 64 threads (2 warps) per output row for latency hiding.
// thread = cg (0..15, 4-channel group) x b-quarter (0..3, 4 batches each).
// fp32 register accumulation -> fp16 store.
// ---------------------------------------------------------------------------
__global__ void __launch_bounds__(256) pool_gather(const float* __restrict__ x) {
    int t = blockIdx.x * blockDim.x + threadIdx.x;
    if (t >= N_OUT * 64) return;
    const int row = t >> 6;
    const int r   = t & 63;
    const int cg  = r & 15;
    const int b0  = (r >> 4) * 4;   // 0,4,8,12

    const int start = g_off[row];
    const int end   = g_off[row + 1];

    float4 acc[4];
#pragma unroll
    for (int b = 0; b < 4; b++) acc[b] = make_float4(0.f, 0.f, 0.f, 0.f);

    const float4* xp = reinterpret_cast<const float4*>(x);
    for (int i = start; i < end; i++) {
        int col = __ldg(g_ecol + i);
        float v = __ldg(g_eval + i);
        const float4* src = xp + ((size_t)b0 * N_IN + col) * 16 + cg;
#pragma unroll
        for (int b = 0; b < 4; b++) {
            float4 xv = src[(size_t)b * N_IN * 16];
            acc[b].x += v * xv.x;
            acc[b].y += v * xv.y;
            acc[b].z += v * xv.z;
            acc[b].w += v * xv.w;
        }
    }
#pragma unroll
    for (int b = 0; b < 4; b++) {
        ushort4 h;
        h.x = __half_as_ushort(__float2half_rn(acc[b].x));
        h.y = __half_as_ushort(__float2half_rn(acc[b].y));
        h.z = __half_as_ushort(__float2half_rn(acc[b].z));
        h.w = __half_as_ushort(__float2half_rn(acc[b].w));
        *reinterpret_cast<ushort4*>(
            g_pooled_h + ((size_t)(b0 + b) * N_OUT + row) * CCH + cg * 4) = h;
    }
}

// ---------------------------------------------------------------------------
// fused spiral gather + fp16 GEMM (B from register fragments) + bias + ELU
// CTA: 128 rows x 64 cols; 256 threads = 8 warps (4x2), warp tile 32x32.
// SMEM: A-only ring, 3 x 16 KB = 48 KB -> 3 CTAs/SM.  (identical to R8)
// ---------------------------------------------------------------------------
#define STAGE_SZ  16384
#define NSTAGE    3
#define GEMM_SMEM (NSTAGE * STAGE_SZ)

__global__ void __launch_bounds__(256, 3) spiral_gemm_mma(
    const int*   __restrict__ sp,
    const float* __restrict__ bias,
    float*       __restrict__ out) {
    extern __shared__ char smem[];
    const uint32_t sbase = smem_u32(smem);

    const int tid = threadIdx.x;
    const int l   = tid & 31;
    const int wid = tid >> 5;
    const int wm  = wid >> 1;
    const int wn  = wid & 1;
    const int b   = blockIdx.y;
    const int n0  = blockIdx.x * 128;

    const int arow  = tid >> 1;
    const int ahalf = tid & 1;
    const int rx    = arow & 7;

    const unsigned short* basePH = g_pooled_h + (size_t)b * N_OUT * CCH;
    const uint2* wfW = g_wfrag + (wn * 4) * 32 + l;

    float acc[2][4][4];
#pragma unroll
    for (int mi = 0; mi < 2; mi++)
#pragma unroll
        for (int nj = 0; nj < 4; nj++)
#pragma unroll
            for (int j = 0; j < 4; j++) acc[mi][nj][j] = 0.f;

    int nn = n0 + arow;
    if (nn >= N_OUT) nn = N_OUT - 1;

    int sidx[SNB];
#pragma unroll
    for (int s = 0; s < SNB; s++) sidx[s] = __ldg(sp + (size_t)nn * SNB + s);

    auto stage = [&](int s) {
        const uint32_t stg = sbase + (s % NSTAGE) * STAGE_SZ;
        const char* srcA =
            (const char*)(basePH + (size_t)sidx[s] * CCH) + ahalf * 64;
        uint32_t dstA = stg + arow * 128;
#pragma unroll
        for (int j = 0; j < 4; j++) {
            int c = ahalf * 4 + j;
            cp16(dstA + ((c ^ rx) << 4), srcA + j * 16);
        }
        cp_commit();
    };

    auto compute = [&](int s) {
        const uint32_t stg = sbase + (s % NSTAGE) * STAGE_SZ;
#pragma unroll
        for (int kk = 0; kk < 4; kk++) {
            uint32_t ah[2][4];
#pragma unroll
            for (int mi = 0; mi < 2; mi++) {
                int row = wm * 32 + mi * 16 + (l & 15);
                int c = kk * 2 + (l >> 4);
                ldm4(ah[mi], stg + row * 128 + ((c ^ (row & 7)) << 4));
            }
            const uint2* wf = wfW + (size_t)(s * 4 + kk) * 8 * 32;
            uint2 bv[4];
#pragma unroll
            for (int nj = 0; nj < 4; nj++) bv[nj] = __ldg(wf + nj * 32);
#pragma unroll
            for (int mi = 0; mi < 2; mi++)
#pragma unroll
                for (int nj = 0; nj < 4; nj++)
                    mma16816(acc[mi][nj], ah[mi], &bv[nj].x);
        }
    };

    stage(0);
    stage(1);
#pragma unroll
    for (int s = 0; s < SNB; s++) {
        cp_wait<1>();
        __syncthreads();
        if (s + 2 < SNB) stage(s + 2);
        else cp_commit();
        compute(s);
    }

    float bias8[4][2];
#pragma unroll
    for (int nj = 0; nj < 4; nj++) {
        int col = wn * 32 + nj * 8 + (l & 3) * 2;
        bias8[nj][0] = __ldg(bias + col);
        bias8[nj][1] = __ldg(bias + col + 1);
    }
#pragma unroll
    for (int mi = 0; mi < 2; mi++) {
#pragma unroll
        for (int half = 0; half < 2; half++) {
            int m = wm * 32 + mi * 16 + (l >> 2) + half * 8;
            int n = n0 + m;
            if (n >= N_OUT) continue;
            float* dst = out + ((size_t)b * N_OUT + n) * CCH;
#pragma unroll
            for (int nj = 0; nj < 4; nj++) {
                int col = wn * 32 + nj * 8 + (l & 3) * 2;
                float t0 = acc[mi][nj][half * 2 + 0] + bias8[nj][0];
                float t1 = acc[mi][nj][half * 2 + 1] + bias8[nj][1];
                float2 o;
                o.x = (t0 > 0.f) ? t0 : (__expf(t0) - 1.f);
                o.y = (t1 > 0.f) ? t1 : (__expf(t1) - 1.f);
                *reinterpret_cast<float2*>(dst + col) = o;
            }
        }
    }
}

// ---------------------------------------------------------------------------
extern "C" void kernel_launch(void* const* d_in, const int* in_sizes, int n_in,
                              void* d_out, int out_size) {
    const float* x    = (const float*)d_in[0];
    const float* tv   = (const float*)d_in[1];
    const int*   tr   = (const int*)d_in[2];
    const int*   tc   = (const int*)d_in[3];
    const int*   sp   = (const int*)d_in[4];
    const float* W    = (const float*)d_in[5];
    const float* bias = (const float*)d_in[6];
    float* out = (float*)d_out;

    static void* cnt_ptr = nullptr;
    static bool attr_set = false;
    if (!attr_set) {
        cudaFuncSetAttribute(spiral_gemm_mma,
                             cudaFuncAttributeMaxDynamicSharedMemorySize,
                             GEMM_SMEM);
        cudaGetSymbolAddress(&cnt_ptr, g_cnt);
        attr_set = true;
    }

    cudaMemsetAsync(cnt_ptr, 0, N_OUT * sizeof(int), 0);
    prep_kernel<<<WFRAG_BLOCKS + HIST_BLOCKS, 256>>>(W, tr);   // launch 1
    csr_scan<<<1, SCAN_T>>>();                                  // launch 2
    csr_scatter<<<(NNZ + 255) / 256, 256>>>(tv, tr, tc);        // launch 3
    pool_gather<<<(N_OUT * 64 + 255) / 256, 256>>>(x);          // launch 4 (profiled)

    dim3 grid((N_OUT + 127) / 128, B_SZ);
    spiral_gemm_mma<<<grid, 256, GEMM_SMEM>>>(sp, bias, out);   // launch 5
}

// round 12
// speedup vs baseline: 1.1056x; 1.0046x over previous
#include <cuda_runtime.h>
#include <cuda_fp16.h>
#include <cstdint>

#define B_SZ  16
#define N_IN  6250
#define N_OUT 25000
#define CCH   64
#define SNB   9
#define NNZ   75000

// fp16 pooled [B][N_OUT][64] = 51.2 MB
__device__ unsigned short g_pooled_h[(size_t)B_SZ * N_OUT * CCH];
// W in mma-fragment order: [s][kk][nb][lane] -> (b0,b1), 72 KB
__device__ uint2 g_wfrag[SNB * 4 * 8 * 32];
// CSR scratch
__device__ int   g_cnt[N_OUT];
__device__ int   g_off[N_OUT + 1];
__device__ int   g_cur[N_OUT];
__device__ int   g_ecol[NNZ];
__device__ float g_eval[NNZ];

// ---------------------------------------------------------------------------
// helpers
// ---------------------------------------------------------------------------
__device__ __forceinline__ uint32_t smem_u32(const void* p) {
    uint32_t a;
    asm("{ .reg .u64 t; cvta.to.shared.u64 t, %1; cvt.u32.u64 %0, t; }"
        : "=r"(a) : "l"(p));
    return a;
}
__device__ __forceinline__ void cp16(uint32_t dst, const void* src) {
    asm volatile("cp.async.cg.shared.global [%0], [%1], 16;"
                 :: "r"(dst), "l"(src) : "memory");
}
__device__ __forceinline__ void cp_commit() {
    asm volatile("cp.async.commit_group;" ::: "memory");
}
template <int N>
__device__ __forceinline__ void cp_wait() {
    asm volatile("cp.async.wait_group %0;" :: "n"(N) : "memory");
}
__device__ __forceinline__ void ldm4(uint32_t* r, uint32_t addr) {
    asm volatile("ldmatrix.sync.aligned.m8n8.x4.shared.b16 {%0,%1,%2,%3}, [%4];"
                 : "=r"(r[0]), "=r"(r[1]), "=r"(r[2]), "=r"(r[3])
                 : "r"(addr));
}
__device__ __forceinline__ void mma16816(float* d, const uint32_t* a,
                                         const uint32_t* b) {
    asm volatile(
        "mma.sync.aligned.m16n8k16.row.col.f32.f16.f16.f32 "
        "{%0,%1,%2,%3},{%4,%5,%6,%7},{%8,%9},{%0,%1,%2,%3};"
        : "+f"(d[0]), "+f"(d[1]), "+f"(d[2]), "+f"(d[3])
        : "r"(a[0]), "r"(a[1]), "r"(a[2]), "r"(a[3]), "r"(b[0]), "r"(b[1]));
}

// ---------------------------------------------------------------------------
// prep: W fragment build (blocks 0..35) + csr_hist (blocks 36..328)
// g_cnt is zeroed by cudaMemsetAsync before this launch.
// ---------------------------------------------------------------------------
#define WFRAG_BLOCKS 36
#define HIST_BLOCKS  ((NNZ + 255) / 256)
__global__ void prep_kernel(const float* __restrict__ W,
                            const int* __restrict__ tr) {
    if (blockIdx.x < WFRAG_BLOCKS) {
        int i = blockIdx.x * 256 + threadIdx.x;
        if (i >= SNB * 4 * 8 * 32) return;
        int l  = i & 31;
        int nb = (i >> 5) & 7;
        int kk = (i >> 8) & 3;
        int s  = i >> 10;
        int n  = nb * 8 + (l >> 2);
        int k0 = s * 64 + kk * 16 + (l & 3) * 2;
        __half2 b0 = __halves2half2(
            __float2half_rn(__ldg(W + (size_t)k0 * 64 + n)),
            __float2half_rn(__ldg(W + (size_t)(k0 + 1) * 64 + n)));
        __half2 b1 = __halves2half2(
            __float2half_rn(__ldg(W + (size_t)(k0 + 8) * 64 + n)),
            __float2half_rn(__ldg(W + (size_t)(k0 + 9) * 64 + n)));
        uint2 v;
        v.x = *reinterpret_cast<uint32_t*>(&b0);
        v.y = *reinterpret_cast<uint32_t*>(&b1);
        g_wfrag[i] = v;
        return;
    }
    int t = (blockIdx.x - WFRAG_BLOCKS) * 256 + threadIdx.x;
    if (t < NNZ) atomicAdd(&g_cnt[__ldg(tr + t)], 1);
}

// ---------------------------------------------------------------------------
// CSR build: scan -> scatter
// ---------------------------------------------------------------------------
#define SCAN_T 1024
#define ROWS_PER_T 25
__global__ void __launch_bounds__(SCAN_T) csr_scan() {
    __shared__ int s[SCAN_T];
    const int t = threadIdx.x;
    const int base = t * ROWS_PER_T;
    int local[ROWS_PER_T];
    int sum = 0;
#pragma unroll
    for (int i = 0; i < ROWS_PER_T; i++) {
        int r = base + i;
        local[i] = (r < N_OUT) ? g_cnt[r] : 0;
        sum += local[i];
    }
    s[t] = sum;
    __syncthreads();
    for (int ofs = 1; ofs < SCAN_T; ofs <<= 1) {
        int v = (t >= ofs) ? s[t - ofs] : 0;
        __syncthreads();
        s[t] += v;
        __syncthreads();
    }
    int run = s[t] - sum;
#pragma unroll
    for (int i = 0; i < ROWS_PER_T; i++) {
        int r = base + i;
        if (r < N_OUT) {
            g_off[r] = run;
            g_cur[r] = run;
            run += local[i];
        }
    }
    if (t == SCAN_T - 1) g_off[N_OUT] = NNZ;
}

__global__ void csr_scatter(const float* __restrict__ tv,
                            const int* __restrict__ tr,
                            const int* __restrict__ tc) {
    int t = blockIdx.x * blockDim.x + threadIdx.x;
    if (t >= NNZ) return;
    int row = __ldg(tr + t);
    int pos = atomicAdd(&g_cur[row], 1);
    g_ecol[pos] = __ldg(tc + t);
    g_eval[pos] = __ldg(tv + t);
}

// ---------------------------------------------------------------------------
// pool_gather: 64 threads (2 warps) per output row.
// thread = cg (0..15) x b-quarter (0..3, 4 batches each). fp32 acc -> fp16.
// ---------------------------------------------------------------------------
__global__ void __launch_bounds__(256) pool_gather(const float* __restrict__ x) {
    int t = blockIdx.x * blockDim.x + threadIdx.x;
    if (t >= N_OUT * 64) return;
    const int row = t >> 6;
    const int r   = t & 63;
    const int cg  = r & 15;
    const int b0  = (r >> 4) * 4;

    const int start = g_off[row];
    const int end   = g_off[row + 1];

    float4 acc[4];
#pragma unroll
    for (int b = 0; b < 4; b++) acc[b] = make_float4(0.f, 0.f, 0.f, 0.f);

    const float4* xp = reinterpret_cast<const float4*>(x);
    for (int i = start; i < end; i++) {
        int col = __ldg(g_ecol + i);
        float v = __ldg(g_eval + i);
        const float4* src = xp + ((size_t)b0 * N_IN + col) * 16 + cg;
#pragma unroll
        for (int b = 0; b < 4; b++) {
            float4 xv = src[(size_t)b * N_IN * 16];
            acc[b].x += v * xv.x;
            acc[b].y += v * xv.y;
            acc[b].z += v * xv.z;
            acc[b].w += v * xv.w;
        }
    }
#pragma unroll
    for (int b = 0; b < 4; b++) {
        ushort4 h;
        h.x = __half_as_ushort(__float2half_rn(acc[b].x));
        h.y = __half_as_ushort(__float2half_rn(acc[b].y));
        h.z = __half_as_ushort(__float2half_rn(acc[b].z));
        h.w = __half_as_ushort(__float2half_rn(acc[b].w));
        *reinterpret_cast<ushort4*>(
            g_pooled_h + ((size_t)(b0 + b) * N_OUT + row) * CCH + cg * 4) = h;
    }
}

// ---------------------------------------------------------------------------
// fused spiral gather + fp16 GEMM + bias + ELU
// CTA: 128 rows x 64 cols; 256 threads = 8 warps (4x2), warp tile 32x32.
// A-only ring, 4 x 16 KB = 64 KB -> 3 CTAs/SM; staging lead = 3 slices.
// B fragments double-buffered across kk to hide LDG latency.
// ---------------------------------------------------------------------------
#define STAGE_SZ  16384
#define NSTAGE    4
#define GEMM_SMEM (NSTAGE * STAGE_SZ)

__global__ void __launch_bounds__(256, 3) spiral_gemm_mma(
    const int*   __restrict__ sp,
    const float* __restrict__ bias,
    float*       __restrict__ out) {
    extern __shared__ char smem[];
    const uint32_t sbase = smem_u32(smem);

    const int tid = threadIdx.x;
    const int l   = tid & 31;
    const int wid = tid >> 5;
    const int wm  = wid >> 1;
    const int wn  = wid & 1;
    const int b   = blockIdx.y;
    const int n0  = blockIdx.x * 128;

    const int arow  = tid >> 1;
    const int ahalf = tid & 1;
    const int rx    = arow & 7;

    const unsigned short* basePH = g_pooled_h + (size_t)b * N_OUT * CCH;
    const uint2* wfW = g_wfrag + (wn * 4) * 32 + l;

    float acc[2][4][4];
#pragma unroll
    for (int mi = 0; mi < 2; mi++)
#pragma unroll
        for (int nj = 0; nj < 4; nj++)
#pragma unroll
            for (int j = 0; j < 4; j++) acc[mi][nj][j] = 0.f;

    int nn = n0 + arow;
    if (nn >= N_OUT) nn = N_OUT - 1;
    const int* sprow = sp + (size_t)nn * SNB;

    auto stage = [&](int s) {
        const uint32_t stg = sbase + (s % NSTAGE) * STAGE_SZ;
        const int idx = __ldg(sprow + s);           // lazy spiral index
        const char* srcA =
            (const char*)(basePH + (size_t)idx * CCH) + ahalf * 64;
        uint32_t dstA = stg + arow * 128;
#pragma unroll
        for (int j = 0; j < 4; j++) {
            int c = ahalf * 4 + j;
            cp16(dstA + ((c ^ rx) << 4), srcA + j * 16);
        }
        cp_commit();
    };

    auto compute = [&](int s) {
        const uint32_t stg = sbase + (s % NSTAGE) * STAGE_SZ;
        const uint2* wfS = wfW + (size_t)(s * 4) * 8 * 32;
        // prefetch kk=0 B fragments
        uint2 bv[2][4];
#pragma unroll
        for (int nj = 0; nj < 4; nj++) bv[0][nj] = __ldg(wfS + nj * 32);
#pragma unroll
        for (int kk = 0; kk < 4; kk++) {
            uint32_t ah[2][4];
#pragma unroll
            for (int mi = 0; mi < 2; mi++) {
                int row = wm * 32 + mi * 16 + (l & 15);
                int c = kk * 2 + (l >> 4);
                ldm4(ah[mi], stg + row * 128 + ((c ^ (row & 7)) << 4));
            }
            // prefetch kk+1 B fragments before consuming kk's
            if (kk < 3) {
                const uint2* wfN = wfS + (size_t)(kk + 1) * 8 * 32;
#pragma unroll
                for (int nj = 0; nj < 4; nj++)
                    bv[(kk + 1) & 1][nj] = __ldg(wfN + nj * 32);
            }
#pragma unroll
            for (int mi = 0; mi < 2; mi++)
#pragma unroll
                for (int nj = 0; nj < 4; nj++)
                    mma16816(acc[mi][nj], ah[mi], &bv[kk & 1][nj].x);
        }
    };

    stage(0);
    stage(1);
    stage(2);
#pragma unroll
    for (int s = 0; s < SNB; s++) {
        cp_wait<2>();
        __syncthreads();
        if (s + 3 < SNB) stage(s + 3);
        else cp_commit();
        compute(s);
    }

    float bias8[4][2];
#pragma unroll
    for (int nj = 0; nj < 4; nj++) {
        int col = wn * 32 + nj * 8 + (l & 3) * 2;
        bias8[nj][0] = __ldg(bias + col);
        bias8[nj][1] = __ldg(bias + col + 1);
    }
#pragma unroll
    for (int mi = 0; mi < 2; mi++) {
#pragma unroll
        for (int half = 0; half < 2; half++) {
            int m = wm * 32 + mi * 16 + (l >> 2) + half * 8;
            int n = n0 + m;
            if (n >= N_OUT) continue;
            float* dst = out + ((size_t)b * N_OUT + n) * CCH;
#pragma unroll
            for (int nj = 0; nj < 4; nj++) {
                int col = wn * 32 + nj * 8 + (l & 3) * 2;
                float t0 = acc[mi][nj][half * 2 + 0] + bias8[nj][0];
                float t1 = acc[mi][nj][half * 2 + 1] + bias8[nj][1];
                float2 o;
                o.x = (t0 > 0.f) ? t0 : (__expf(t0) - 1.f);
                o.y = (t1 > 0.f) ? t1 : (__expf(t1) - 1.f);
                *reinterpret_cast<float2*>(dst + col) = o;
            }
        }
    }
}

// ---------------------------------------------------------------------------
extern "C" void kernel_launch(void* const* d_in, const int* in_sizes, int n_in,
                              void* d_out, int out_size) {
    const float* x    = (const float*)d_in[0];
    const float* tv   = (const float*)d_in[1];
    const int*   tr   = (const int*)d_in[2];
    const int*   tc   = (const int*)d_in[3];
    const int*   sp   = (const int*)d_in[4];
    const float* W    = (const float*)d_in[5];
    const float* bias = (const float*)d_in[6];
    float* out = (float*)d_out;

    static void* cnt_ptr = nullptr;
    static bool attr_set = false;
    if (!attr_set) {
        cudaFuncSetAttribute(spiral_gemm_mma,
                             cudaFuncAttributeMaxDynamicSharedMemorySize,
                             GEMM_SMEM);
        cudaGetSymbolAddress(&cnt_ptr, g_cnt);
        attr_set = true;
    }

    cudaMemsetAsync(cnt_ptr, 0, N_OUT * sizeof(int), 0);
    prep_kernel<<<WFRAG_BLOCKS + HIST_BLOCKS, 256>>>(W, tr);
    csr_scan<<<1, SCAN_T>>>();
    csr_scatter<<<(NNZ + 255) / 256, 256>>>(tv, tr, tc);
    pool_gather<<<(N_OUT * 64 + 255) / 256, 256>>>(x);

    dim3 grid((N_OUT + 127) / 128, B_SZ);
    spiral_gemm_mma<<<grid, 256, GEMM_SMEM>>>(sp, bias, out);
}